// round 15
// baseline (speedup 1.0000x reference)
#include <cuda_runtime.h>
#include <math.h>

#define C_SIZE 1000
#define NCHUNK 250          // float4 chunks per row
#define TAIL_LANES 26       // lanes 0..25 own chunk 224+lane (j=7)
#define CTAS 4              // CTAs per SM (128-reg budget)
#define GRID_BLKS (148 * CTAS)

// Device-global scratch (no allocations allowed).
// INVARIANT: zero at kernel entry; the last-finishing block re-zeroes on the
// way out, so graph replays stay correct.
__device__ float g_conf[C_SIZE];
__device__ int   g_counts[C_SIZE];
__device__ int   g_done;

__global__ __launch_bounds__(128, CTAS)
void mdca_fused_kernel(const float* __restrict__ logits,
                       const int*   __restrict__ tgt,
                       int B, float* __restrict__ res) {
    __shared__ float sh_fin[4];
    __shared__ int   sh_last;

    const int t    = threadIdx.x;
    const int lane = t & 31;
    const int wid  = t >> 5;

    // ---------------- phase 0: target bincount (grid-strided) -------------
    for (int i = blockIdx.x * 128 + t; i < B; i += (int)gridDim.x * 128) {
        int c = tgt[i];
        c = (c < 0) ? 0 : ((c >= C_SIZE) ? C_SIZE - 1 : c);
        atomicAdd(&g_counts[c], 1);
    }

    // ---------------- phase 1: warp-autonomous, 2 rows per iteration -------
    // Lane owns float4 chunks {lane+32j : j=0..6} and (lane<26) 224+lane in
    // EVERY row -> one register-resident accumulator set per lane.
    // No block barriers in the hot loop; reductions are warp shfl only.
    const bool  m7    = (lane < TAIL_LANES);
    const float mask7 = m7 ? 1.0f : 0.0f;    // kills exp2(0)=1 on tail chunk
    const float LOG2E = 1.4426950408889634f;

    const int gw = blockIdx.x * 4 + wid;          // global warp id
    const int W  = (int)gridDim.x * 4;            // total warps

    float4 acc[8];
    #pragma unroll
    for (int j = 0; j < 8; j++) acc[j] = make_float4(0.f, 0.f, 0.f, 0.f);

    for (int row0 = gw * 2; row0 < B; row0 += W * 2) {
        const int  rowb = row0 + 1;
        const bool okb  = (rowb < B);

        const float4* __restrict__ rpa =
            (const float4*)(logits + (size_t)row0 * C_SIZE);
        const float4* __restrict__ rpb =
            (const float4*)(logits + (size_t)(okb ? rowb : row0) * C_SIZE);

        // ---- front-batched loads: 16 independent LDG.128 ----
        float4 va[8], vb[8];
        #pragma unroll
        for (int j = 0; j < 7; j++) va[j] = rpa[lane + 32 * j];
        va[7] = m7 ? rpa[224 + lane] : make_float4(0.f, 0.f, 0.f, 0.f);
        #pragma unroll
        for (int j = 0; j < 7; j++) vb[j] = rpb[lane + 32 * j];
        vb[7] = m7 ? rpb[224 + lane] : make_float4(0.f, 0.f, 0.f, 0.f);

        // ---- sum of squares, both rows (independent chains) ----
        float sa0 = 0.f, sa1 = 0.f, sa2 = 0.f, sa3 = 0.f;
        float sb0 = 0.f, sb1 = 0.f, sb2 = 0.f, sb3 = 0.f;
        #pragma unroll
        for (int j = 0; j < 8; j++) {
            sa0 = fmaf(va[j].x, va[j].x, sa0);
            sa1 = fmaf(va[j].y, va[j].y, sa1);
            sa2 = fmaf(va[j].z, va[j].z, sa2);
            sa3 = fmaf(va[j].w, va[j].w, sa3);
            sb0 = fmaf(vb[j].x, vb[j].x, sb0);
            sb1 = fmaf(vb[j].y, vb[j].y, sb1);
            sb2 = fmaf(vb[j].z, vb[j].z, sb2);
            sb3 = fmaf(vb[j].w, vb[j].w, sb3);
        }
        float ssa = (sa0 + sa1) + (sa2 + sa3);
        float ssb = (sb0 + sb1) + (sb2 + sb3);
        #pragma unroll
        for (int o = 16; o > 0; o >>= 1) {
            ssa += __shfl_xor_sync(0xffffffffu, ssa, o);
            ssb += __shfl_xor_sync(0xffffffffu, ssb, o);
        }

        const float aa = LOG2E * rsqrtf(fmaxf(ssa, 1e-30f));
        const float ab = LOG2E * rsqrtf(fmaxf(ssb, 1e-30f));

        // ---- exponentials in place + per-lane sums (both rows) ----
        float ea0 = 0.f, ea1 = 0.f, eb0 = 0.f, eb1 = 0.f;
        #pragma unroll
        for (int j = 0; j < 8; j++) {
            float4 w = va[j];
            w.x = exp2f(w.x * aa); w.y = exp2f(w.y * aa);
            w.z = exp2f(w.z * aa); w.w = exp2f(w.w * aa);
            if (j == 7) { w.x *= mask7; w.y *= mask7; w.z *= mask7; w.w *= mask7; }
            va[j] = w;
            ea0 += w.x + w.y; ea1 += w.z + w.w;

            float4 u = vb[j];
            u.x = exp2f(u.x * ab); u.y = exp2f(u.y * ab);
            u.z = exp2f(u.z * ab); u.w = exp2f(u.w * ab);
            if (j == 7) { u.x *= mask7; u.y *= mask7; u.z *= mask7; u.w *= mask7; }
            vb[j] = u;
            eb0 += u.x + u.y; eb1 += u.z + u.w;
        }
        float sea = ea0 + ea1;
        float seb = eb0 + eb1;
        #pragma unroll
        for (int o = 16; o > 0; o >>= 1) {
            sea += __shfl_xor_sync(0xffffffffu, sea, o);
            seb += __shfl_xor_sync(0xffffffffu, seb, o);
        }

        const float rsa = __fdividef(1.0f, sea);
        const float rsb = okb ? __fdividef(1.0f, seb) : 0.0f;

        // ---- accumulate probabilities (1 FFMA per value per row) ----
        #pragma unroll
        for (int j = 0; j < 8; j++) {
            acc[j].x = fmaf(va[j].x, rsa, fmaf(vb[j].x, rsb, acc[j].x));
            acc[j].y = fmaf(va[j].y, rsa, fmaf(vb[j].y, rsb, acc[j].y));
            acc[j].z = fmaf(va[j].z, rsa, fmaf(vb[j].z, rsb, acc[j].z));
            acc[j].w = fmaf(va[j].w, rsa, fmaf(vb[j].w, rsb, acc[j].w));
        }
    }

    // ---------------- phase 2: flush per-warp partials ---------------------
    #pragma unroll
    for (int j = 0; j < 8; j++) {
        const int chunk = (j < 7) ? (lane + 32 * j) : (224 + lane);
        if (j < 7 || m7) {
            const int c = 4 * chunk;
            atomicAdd(&g_conf[c + 0], acc[j].x);
            atomicAdd(&g_conf[c + 1], acc[j].y);
            atomicAdd(&g_conf[c + 2], acc[j].z);
            atomicAdd(&g_conf[c + 3], acc[j].w);
        }
    }
    __threadfence();
    __syncthreads();

    // ---------------- phase 3: last block computes the scalar --------------
    if (t == 0)
        sh_last = (atomicAdd(&g_done, 1) == (int)gridDim.x - 1) ? 1 : 0;
    __syncthreads();
    if (!sh_last) return;

    // atomicExch reads the final value AND re-zeroes for the next replay.
    float d = 0.0f;
    #pragma unroll
    for (int j = 0; j < 8; j++) {
        int c = t + 128 * j;
        if (c < C_SIZE) {
            float cf = atomicExch(&g_conf[c], 0.0f);
            int   ct = atomicExch(&g_counts[c], 0);
            d += fabsf(cf - (float)ct);
        }
    }
    #pragma unroll
    for (int o = 16; o > 0; o >>= 1)
        d += __shfl_xor_sync(0xffffffffu, d, o);
    if (lane == 0) sh_fin[wid] = d;
    __syncthreads();
    if (t == 0) {
        float tot = (sh_fin[0] + sh_fin[1]) + (sh_fin[2] + sh_fin[3]);
        res[0] = tot / ((float)B * (float)C_SIZE);
        g_done = 0;                       // reset for next graph replay
        __threadfence();
    }
}

// ---------------------------------------------------------------------------
extern "C" void kernel_launch(void* const* d_in, const int* in_sizes, int n_in,
                              void* d_out, int out_size) {
    // Robust input resolution: the [B,1000] fp32 logits tensor is the larger
    // input; the target vector is the smaller one.
    int io = 0, it = 1;
    if (n_in >= 2 && in_sizes[1] > in_sizes[0]) { io = 1; it = 0; }

    const float* logits = (const float*)d_in[io];  // [B, 1000] fp32
    const int*   tgt    = (const int*)d_in[it];    // [B] int32
    float* res = (float*)d_out;

    const int B = in_sizes[it];

    mdca_fused_kernel<<<GRID_BLKS, 128>>>(logits, tgt, B, res);
}

// round 17
// speedup vs baseline: 1.6302x; 1.6302x over previous
#include <cuda_runtime.h>
#include <math.h>

#define C_SIZE 1000
#define NCHUNK 250          // float4 chunks per row
#define ROWS   4            // rows per loop iteration
#define CTAS   9            // CTAs per SM (regs <= 56, no spills)
#define GRID_BLKS (148 * CTAS)

// Device-global scratch (no allocations allowed).
// INVARIANT: zero at kernel entry; the last-finishing block re-zeroes on the
// way out, so graph replays stay correct.
__device__ float g_conf[C_SIZE];
__device__ int   g_counts[C_SIZE];
__device__ int   g_done;

__global__ __launch_bounds__(128, CTAS)
void mdca_fused_kernel(const float* __restrict__ logits,
                       const int*   __restrict__ tgt,
                       int B, float* __restrict__ res) {
    // Per-CTA class accumulators in smem: thread t exclusively owns
    // sacc[t] (classes 4t..4t+3) and sacc[128+t] (classes 512+4t..).
    __shared__ float4 sacc[NCHUNK];
    __shared__ float  sh_ss[ROWS][4];
    __shared__ float  sh_se[ROWS][4];
    __shared__ float  sh_fin[4];
    __shared__ int    sh_last;

    const int t    = threadIdx.x;
    const int lane = t & 31;
    const int wid  = t >> 5;

    // zero the smem accumulators
    sacc[t] = make_float4(0.f, 0.f, 0.f, 0.f);
    if (128 + t < NCHUNK) sacc[128 + t] = make_float4(0.f, 0.f, 0.f, 0.f);

    // ---------------- phase 0: target bincount (grid-strided) -------------
    for (int i = blockIdx.x * 128 + t; i < B; i += (int)gridDim.x * 128) {
        int c = tgt[i];
        c = (c < 0) ? 0 : ((c >= C_SIZE) ? C_SIZE - 1 : c);
        atomicAdd(&g_counts[c], 1);
    }
    __syncthreads();   // sacc zeroing + bincount done before hot loop

    // ---------------- phase 1: 4 rows per iteration ------------------------
    const int   k1    = 128 + t;
    const bool  has1  = (k1 < NCHUNK);
    const float mask1 = has1 ? 1.0f : 0.0f;   // kills exp2(0)=1 on tail threads
    const float LOG2E = 1.4426950408889634f;

    for (int row0 = blockIdx.x * ROWS; row0 < B;
         row0 += (int)gridDim.x * ROWS) {

        // ---- front-batched loads: 8 independent LDG.128 per thread ----
        float4 v[2 * ROWS];
        #pragma unroll
        for (int r = 0; r < ROWS; r++) {
            const int row = row0 + r;
            const bool ok = (row < B);
            const float4* __restrict__ rp =
                (const float4*)(logits + (size_t)row * C_SIZE);
            v[2 * r]     = ok ? rp[t]
                              : make_float4(0.f, 0.f, 0.f, 0.f);
            v[2 * r + 1] = (ok && has1) ? rp[k1]
                              : make_float4(0.f, 0.f, 0.f, 0.f);
        }

        // ---- sum of squares per row ----
        float ss[ROWS];
        #pragma unroll
        for (int r = 0; r < ROWS; r++) {
            float4 w0 = v[2 * r], w1 = v[2 * r + 1];
            float s;
            s = w0.x * w0.x;
            s = fmaf(w0.y, w0.y, s); s = fmaf(w0.z, w0.z, s);
            s = fmaf(w0.w, w0.w, s);
            s = fmaf(w1.x, w1.x, s); s = fmaf(w1.y, w1.y, s);
            s = fmaf(w1.z, w1.z, s); s = fmaf(w1.w, w1.w, s);
            ss[r] = s;
        }
        #pragma unroll
        for (int o = 16; o > 0; o >>= 1) {
            #pragma unroll
            for (int r = 0; r < ROWS; r++)
                ss[r] += __shfl_xor_sync(0xffffffffu, ss[r], o);
        }
        if (lane == 0) {
            #pragma unroll
            for (int r = 0; r < ROWS; r++) sh_ss[r][wid] = ss[r];
        }
        __syncthreads();                                   // barrier 1

        // ---- exponentials in place + per-row sums ----
        float se[ROWS];
        #pragma unroll
        for (int r = 0; r < ROWS; r++) {
            float s = (sh_ss[r][0] + sh_ss[r][1]) +
                      (sh_ss[r][2] + sh_ss[r][3]);
            const float a = LOG2E * rsqrtf(fmaxf(s, 1e-30f));
            float4 w0 = v[2 * r], w1 = v[2 * r + 1];
            float4 e0, e1;
            e0.x = exp2f(w0.x * a); e0.y = exp2f(w0.y * a);
            e0.z = exp2f(w0.z * a); e0.w = exp2f(w0.w * a);
            e1.x = mask1 * exp2f(w1.x * a); e1.y = mask1 * exp2f(w1.y * a);
            e1.z = mask1 * exp2f(w1.z * a); e1.w = mask1 * exp2f(w1.w * a);
            v[2 * r] = e0; v[2 * r + 1] = e1;
            se[r] = ((e0.x + e0.y) + (e0.z + e0.w)) +
                    ((e1.x + e1.y) + (e1.z + e1.w));
        }
        #pragma unroll
        for (int o = 16; o > 0; o >>= 1) {
            #pragma unroll
            for (int r = 0; r < ROWS; r++)
                se[r] += __shfl_xor_sync(0xffffffffu, se[r], o);
        }
        if (lane == 0) {
            #pragma unroll
            for (int r = 0; r < ROWS; r++) sh_se[r][wid] = se[r];
        }
        __syncthreads();                                   // barrier 2

        // ---- accumulate probabilities into smem (exclusive slots) ----
        float rs[ROWS];
        #pragma unroll
        for (int r = 0; r < ROWS; r++) {
            float s = (sh_se[r][0] + sh_se[r][1]) +
                      (sh_se[r][2] + sh_se[r][3]);
            rs[r] = (row0 + r < B) ? __fdividef(1.0f, s) : 0.0f;
        }
        {
            float4 a0 = sacc[t];
            #pragma unroll
            for (int r = 0; r < ROWS; r++) {
                a0.x = fmaf(v[2 * r].x, rs[r], a0.x);
                a0.y = fmaf(v[2 * r].y, rs[r], a0.y);
                a0.z = fmaf(v[2 * r].z, rs[r], a0.z);
                a0.w = fmaf(v[2 * r].w, rs[r], a0.w);
            }
            sacc[t] = a0;
        }
        if (has1) {
            float4 a1 = sacc[k1];
            #pragma unroll
            for (int r = 0; r < ROWS; r++) {
                a1.x = fmaf(v[2 * r + 1].x, rs[r], a1.x);
                a1.y = fmaf(v[2 * r + 1].y, rs[r], a1.y);
                a1.z = fmaf(v[2 * r + 1].z, rs[r], a1.z);
                a1.w = fmaf(v[2 * r + 1].w, rs[r], a1.w);
            }
            sacc[k1] = a1;
        }
    }

    // ---------------- phase 2: flush per-block partials --------------------
    {
        float4 a0 = sacc[t];
        const int c0 = 4 * t;
        atomicAdd(&g_conf[c0 + 0], a0.x);
        atomicAdd(&g_conf[c0 + 1], a0.y);
        atomicAdd(&g_conf[c0 + 2], a0.z);
        atomicAdd(&g_conf[c0 + 3], a0.w);
        if (has1) {
            float4 a1 = sacc[k1];
            const int c1 = 4 * k1;
            atomicAdd(&g_conf[c1 + 0], a1.x);
            atomicAdd(&g_conf[c1 + 1], a1.y);
            atomicAdd(&g_conf[c1 + 2], a1.z);
            atomicAdd(&g_conf[c1 + 3], a1.w);
        }
    }
    __threadfence();
    __syncthreads();

    // ---------------- phase 3: last block computes the scalar --------------
    if (t == 0)
        sh_last = (atomicAdd(&g_done, 1) == (int)gridDim.x - 1) ? 1 : 0;
    __syncthreads();
    if (!sh_last) return;

    // atomicExch reads the final value AND re-zeroes for the next replay.
    float d = 0.0f;
    #pragma unroll
    for (int j = 0; j < 8; j++) {
        int c = t + 128 * j;
        if (c < C_SIZE) {
            float cf = atomicExch(&g_conf[c], 0.0f);
            int   ct = atomicExch(&g_counts[c], 0);
            d += fabsf(cf - (float)ct);
        }
    }
    #pragma unroll
    for (int o = 16; o > 0; o >>= 1)
        d += __shfl_xor_sync(0xffffffffu, d, o);
    if (lane == 0) sh_fin[wid] = d;
    __syncthreads();
    if (t == 0) {
        float tot = (sh_fin[0] + sh_fin[1]) + (sh_fin[2] + sh_fin[3]);
        res[0] = tot / ((float)B * (float)C_SIZE);
        g_done = 0;                       // reset for next graph replay
        __threadfence();
    }
}

// ---------------------------------------------------------------------------
extern "C" void kernel_launch(void* const* d_in, const int* in_sizes, int n_in,
                              void* d_out, int out_size) {
    // Robust input resolution: the [B,1000] fp32 logits tensor is the larger
    // input; the target vector is the smaller one.
    int io = 0, it = 1;
    if (n_in >= 2 && in_sizes[1] > in_sizes[0]) { io = 1; it = 0; }

    const float* logits = (const float*)d_in[io];  // [B, 1000] fp32
    const int*   tgt    = (const int*)d_in[it];    // [B] int32
    float* res = (float*)d_out;

    const int B = in_sizes[it];

    mdca_fused_kernel<<<GRID_BLKS, 128>>>(logits, tgt, B, res);
}